// round 16
// baseline (speedup 1.0000x reference)
#include <cuda_runtime.h>
#include <math.h>
#include <float.h>

#define BATCH 16
#define NPTS  2048
#define DIM   64
#define SPLIT 8
#define GROUPS 4
#define SPLIT_EFF (SPLIT * GROUPS)   // 32 partials per batch
#define CHUNK (NPTS / SPLIT)         // 256 rows per CTA
#define GROWS (CHUNK / GROUPS)       // 64 rows per group
#define STR 68
#define ETHREADS 512

#define EIG_SMEM_FLOATS (4 * DIM * STR)
#define EIG_SMEM_BYTES  (EIG_SMEM_FLOATS * 4)
#define PM_SMEM_BYTES   (CHUNK * DIM * 4)   // 64 KB

// scratch for partial maxima: 16 * 32 * 4096 * 4B = 8 MB
__device__ float g_partial[BATCH][SPLIT_EFF][DIM * DIM];

// ---------------------------------------------------------------------------
// Kernel 1: partial max of outer products. grid=(SPLIT,BATCH), 256 threads.
// ---------------------------------------------------------------------------
__global__ void __launch_bounds__(256) sop_partial_max(const float* __restrict__ x) {
    extern __shared__ float xs[];   // [CHUNK][DIM]
    const int b = blockIdx.y;
    const int c = blockIdx.x;
    const int tid = threadIdx.x;

    const float* xp = x + ((size_t)b * NPTS + (size_t)c * CHUNK) * DIM;
    for (int e = tid * 4; e < CHUNK * DIM; e += 256 * 4) {
        float4 v = *(const float4*)(xp + e);
        *(float4*)(xs + e) = v;
    }
    __syncthreads();

    const int g  = tid >> 6;
    const int gt = tid & 63;
    const int ti = (gt >> 3) * 8;
    const int tj = (gt & 7) * 8;
    const float* base = xs + g * GROWS * DIM;

    float acc[8][8];
#pragma unroll
    for (int a = 0; a < 8; a++)
#pragma unroll
        for (int bb = 0; bb < 8; bb++) acc[a][bb] = -FLT_MAX;

#pragma unroll 4
    for (int n = 0; n < GROWS; n++) {
        const float4 vi0 = *(const float4*)&base[n * DIM + ti];
        const float4 vi1 = *(const float4*)&base[n * DIM + ti + 4];
        const float4 vj0 = *(const float4*)&base[n * DIM + tj];
        const float4 vj1 = *(const float4*)&base[n * DIM + tj + 4];
        const float fi[8] = {vi0.x, vi0.y, vi0.z, vi0.w, vi1.x, vi1.y, vi1.z, vi1.w};
        const float fj[8] = {vj0.x, vj0.y, vj0.z, vj0.w, vj1.x, vj1.y, vj1.z, vj1.w};
#pragma unroll
        for (int a = 0; a < 8; a++)
#pragma unroll
            for (int bb = 0; bb < 8; bb++)
                acc[a][bb] = fmaxf(acc[a][bb], fi[a] * fj[bb]);
    }

    float* outp = g_partial[b][c * GROUPS + g];
#pragma unroll
    for (int a = 0; a < 8; a++) {
        *(float4*)(outp + (ti + a) * DIM + tj) =
            make_float4(acc[a][0], acc[a][1], acc[a][2], acc[a][3]);
        *(float4*)(outp + (ti + a) * DIM + tj + 4) =
            make_float4(acc[a][4], acc[a][5], acc[a][6], acc[a][7]);
    }
}

// ---------------------------------------------------------------------------
__device__ __forceinline__ float block_reduce_sum(float v, float* red, int tid) {
    __syncthreads();
#pragma unroll
    for (int o = 16; o; o >>= 1) v += __shfl_down_sync(0xffffffffu, v, o);
    if ((tid & 31) == 0) red[tid >> 5] = v;
    __syncthreads();
    if (tid < 32) {
        float w = (tid < 16) ? red[tid] : 0.f;
#pragma unroll
        for (int o = 8; o; o >>= 1) w += __shfl_down_sync(0xffffffffu, w, o);
        if (tid == 0) red[0] = w;
    }
    __syncthreads();
    return red[0];
}

__device__ __forceinline__ float offdiag_partial(const float* A, int tid) {
    const int e0 = tid * 8;
    const int i = e0 >> 6, j0 = e0 & 63;
    float off = 0.f;
#pragma unroll
    for (int u = 0; u < 8; u++) {
        const float v = A[i * STR + j0 + u];
        off += (i != j0 + u) ? v * v : 0.f;
    }
    return off;
}

// ---------------------------------------------------------------------------
// One Jacobi tournament round: src -> dst. All smem loads issued up-front;
// next-round indices computed in the MUFU/SHFL latency shadow; Qt stores
// issue before A stores. Arithmetic per element identical to prior rounds.
// ---------------------------------------------------------------------------
struct JState {
    int pl, ql, plS, qlS;          // lane's column pair
    int pSA, qSA, pSB, qSB;        // warp's row-pair offsets
};

__device__ __forceinline__ void jacobi_round(
    const float* __restrict__ Ac, float* __restrict__ An,
    float* __restrict__ Qts, JState& st, int warp, int lane)
{
    // ======== front-loaded loads (all ready at round start) ========
    const float app = Ac[st.plS + st.pl];
    const float aqq = Ac[st.qlS + st.ql];
    const float apq = Ac[st.plS + st.ql];

    const float aA_pp = Ac[st.pSA + st.pl];
    const float aA_pq = Ac[st.pSA + st.ql];
    const float aA_qp = Ac[st.qSA + st.pl];
    const float aA_qq = Ac[st.qSA + st.ql];

    const float aB_pp = Ac[st.pSB + st.pl];
    const float aB_pq = Ac[st.pSB + st.ql];
    const float aB_qp = Ac[st.qSB + st.pl];
    const float aB_qq = Ac[st.qSB + st.ql];

    const int   pSq = (lane < 16) ? st.pSA : st.pSB;
    const int   qSq = (lane < 16) ? st.qSA : st.qSB;
    const int   sub = (lane & 15) * 4;
    float4* Qp = (float4*)(Qts + pSq + sub);
    float4* Qq = (float4*)(Qts + qSq + sub);
    const float4 qp = *Qp;
    const float4 qq = *Qq;

    // ======== next-round indices (independent; fills LDS/MUFU shadow) ====
    int npl = st.pl, nplS = st.plS;
    if (lane) {
        npl  = (st.pl  == 62)       ? 0 : st.pl + 1;
        nplS = (st.plS == 62 * STR) ? 0 : st.plS + STR;
    }
    const int nql  = (st.ql  == 62)       ? 0 : st.ql + 1;
    const int nqlS = (st.qlS == 62 * STR) ? 0 : st.qlS + STR;
    int npSA = st.pSA;
    if (warp) npSA = (st.pSA == 62 * STR) ? 0 : st.pSA + STR;
    const int nqSA = (st.qSA == 62 * STR) ? 0 : st.qSA + STR;
    const int npSB = (st.pSB == 62 * STR) ? 0 : st.pSB + STR;
    const int nqSB = (st.qSB == 62 * STR) ? 0 : st.qSB + STR;

    // ======== rotation params for column pair 'lane' (2 MUFU) ========
    const float d = aqq - app;
    const float g = apq + apq;
    const float rr = fmaf(d, d, g * g);
    const float ir = __frsqrt_rn(rr);
    const float xv = fabsf(d) * ir;
    const float yv = fmaf(0.5f, xv, 0.5f);
    const float ic = __frsqrt_rn(yv);
    float c = yv * ic;
    float s = 0.5f * g * ir * ic;
    s = __int_as_float(__float_as_int(s) ^
                       (__float_as_int(d) & 0x80000000));
    if (rr < 1e-40f) { c = 1.f; s = 0.f; }

    // row-pair params via shfl
    const float cA = __shfl_sync(0xffffffffu, c, warp);
    const float sA = __shfl_sync(0xffffffffu, s, warp);
    const float cB = __shfl_sync(0xffffffffu, c, warp + 16);
    const float sB = __shfl_sync(0xffffffffu, s, warp + 16);

    // ======== Qt update + stores FIRST (early drain) ========
    {
        const float cq = (lane < 16) ? cA : cB;
        const float sq = (lane < 16) ? sA : sB;
        *Qp = make_float4(fmaf(cq, qp.x, -sq * qq.x),
                          fmaf(cq, qp.y, -sq * qq.y),
                          fmaf(cq, qp.z, -sq * qq.z),
                          fmaf(cq, qp.w, -sq * qq.w));
        *Qq = make_float4(fmaf(sq, qp.x, cq * qq.x),
                          fmaf(sq, qp.y, cq * qq.y),
                          fmaf(sq, qp.z, cq * qq.z),
                          fmaf(sq, qp.w, cq * qq.w));
    }

    // ======== A: fused two-sided 2x2 updates (reg-resident inputs) ========
    {
        const float rp_p = fmaf(cA, aA_pp, -sA * aA_qp);
        const float rp_q = fmaf(cA, aA_pq, -sA * aA_qq);
        const float rq_p = fmaf(sA, aA_pp,  cA * aA_qp);
        const float rq_q = fmaf(sA, aA_pq,  cA * aA_qq);
        An[st.pSA + st.pl] = fmaf(c, rp_p, -s * rp_q);
        An[st.pSA + st.ql] = fmaf(s, rp_p,  c * rp_q);
        An[st.qSA + st.pl] = fmaf(c, rq_p, -s * rq_q);
        An[st.qSA + st.ql] = fmaf(s, rq_p,  c * rq_q);
    }
    {
        const float rp_p = fmaf(cB, aB_pp, -sB * aB_qp);
        const float rp_q = fmaf(cB, aB_pq, -sB * aB_qq);
        const float rq_p = fmaf(sB, aB_pp,  cB * aB_qp);
        const float rq_q = fmaf(sB, aB_pq,  cB * aB_qq);
        An[st.pSB + st.pl] = fmaf(c, rp_p, -s * rp_q);
        An[st.pSB + st.ql] = fmaf(s, rp_p,  c * rp_q);
        An[st.qSB + st.pl] = fmaf(c, rq_p, -s * rq_q);
        An[st.qSB + st.ql] = fmaf(s, rq_p,  c * rq_q);
    }

    // ======== commit advanced indices (register moves only) ========
    st.pl = npl;  st.plS = nplS;
    st.ql = nql;  st.qlS = nqlS;
    st.pSA = npSA; st.qSA = nqSA;
    st.pSB = npSB; st.qSB = nqSB;

    __syncthreads();
}

// ---------------------------------------------------------------------------
// Kernel 2: 4 Jacobi sweeps + segmented valve 5th sweep (checks every 8
// rounds), 2nd-order Daleckii-Krein sqrt, Qt^T F2 Qt, L2 normalize.
// 512 threads / 16 warps, one CTA per batch.
// ---------------------------------------------------------------------------
__global__ void __launch_bounds__(ETHREADS) sop_eig_kernel(float* __restrict__ out) {
    extern __shared__ float dsm[];
    float* Abuf0 = dsm;
    float* Abuf1 = dsm + DIM * STR;
    float* Qts   = dsm + 2 * DIM * STR;
    float* Gbuf  = dsm + 3 * DIM * STR;

    __shared__ float red[16];
    __shared__ float gs[DIM];
    __shared__ float dsv[DIM];

    const int b = blockIdx.x;
    const int tid = threadIdx.x;
    const int warp = tid >> 5;
    const int lane = tid & 31;

    // ---- reduce partials into A0 (float4), init Qt = I, accumulate frob2 ----
    float frloc = 0.f;
    {
        const int e0 = tid * 8;
        const int i = e0 >> 6, j0 = e0 & 63;
        float4 m0 = make_float4(-FLT_MAX, -FLT_MAX, -FLT_MAX, -FLT_MAX);
        float4 m1 = m0;
#pragma unroll 8
        for (int c = 0; c < SPLIT_EFF; c++) {
            const float4* gp = (const float4*)&g_partial[b][c][e0];
            float4 v0 = gp[0], v1 = gp[1];
            m0.x = fmaxf(m0.x, v0.x); m0.y = fmaxf(m0.y, v0.y);
            m0.z = fmaxf(m0.z, v0.z); m0.w = fmaxf(m0.w, v0.w);
            m1.x = fmaxf(m1.x, v1.x); m1.y = fmaxf(m1.y, v1.y);
            m1.z = fmaxf(m1.z, v1.z); m1.w = fmaxf(m1.w, v1.w);
        }
        *(float4*)&Abuf0[i * STR + j0]     = m0;
        *(float4*)&Abuf0[i * STR + j0 + 4] = m1;
        frloc = m0.x*m0.x + m0.y*m0.y + m0.z*m0.z + m0.w*m0.w
              + m1.x*m1.x + m1.y*m1.y + m1.z*m1.z + m1.w*m1.w;
        float4 id0 = make_float4((i == j0+0)?1.f:0.f, (i == j0+1)?1.f:0.f,
                                 (i == j0+2)?1.f:0.f, (i == j0+3)?1.f:0.f);
        float4 id1 = make_float4((i == j0+4)?1.f:0.f, (i == j0+5)?1.f:0.f,
                                 (i == j0+6)?1.f:0.f, (i == j0+7)?1.f:0.f);
        *(float4*)&Qts[i * STR + j0]     = id0;
        *(float4*)&Qts[i * STR + j0 + 4] = id1;
    }
    const float frob2 = block_reduce_sum(frloc, red, tid) + 1e-30f;

    // ---- persistent tournament indices ----
    JState st;
    if (lane == 0) { st.pl = 63; st.ql = 0; }
    else           { st.pl = lane; st.ql = 63 - lane; }
    st.plS = st.pl * STR;
    st.qlS = st.ql * STR;
    if (warp == 0) { st.pSA = 63 * STR; st.qSA = 0; }
    else           { st.pSA = warp * STR; st.qSA = (63 - warp) * STR; }
    st.pSB = (warp + 16) * STR;
    st.qSB = (47 - warp) * STR;

    // ---- 4 sweeps = 252 rounds (even), unrolled x2; ends in Abuf0 ----
    for (int rp = 0; rp < 126; rp++) {
        jacobi_round(Abuf0, Abuf1, Qts, st, warp, lane);
        jacobi_round(Abuf1, Abuf0, Qts, st, warp, lane);
    }

    // ---- valve: segmented 5th sweep (check every 8 rounds) ----
    float* Ac = Abuf0;
    float* An = Abuf1;
    {
        const float thr = 3e-5f * frob2;
        const float offt = block_reduce_sum(offdiag_partial(Ac, tid), red, tid);
        if (offt >= thr) {
            int done = 0;
#pragma unroll 1
            for (int seg = 0; seg < 8; seg++) {
                const int stop = (seg == 7) ? 63 : 8 * (seg + 1);
#pragma unroll 1
                for (; done < stop; done++) {
                    jacobi_round(Ac, An, Qts, st, warp, lane);
                    float* t = Ac; Ac = An; An = t;
                }
                const float o2 = block_reduce_sum(offdiag_partial(Ac, tid),
                                                  red, tid);
                if (o2 < thr) break;
            }
        }
    }

    // =======================================================================
    // 2nd-order Daleckii-Krein sqrt of A = D + E, msqrt = Qt^T (F+S) Qt
    // =======================================================================

    if (tid < DIM) {
        const float lam = Ac[tid * STR + tid];
        dsv[tid] = lam;
        gs[tid] = copysignf(sqrtf(fabsf(lam)), lam);
    }
    __syncthreads();

    // ---- build F into An (thread: row i, 8 cols) ----
    {
        const int i = tid >> 3;
        const int j0 = (tid & 7) * 8;
        const float gi = gs[i];
        const float di = dsv[i];
#pragma unroll
        for (int u = 0; u < 8; u++) {
            const int j = j0 + u;
            const float gj = gs[j];
            float DD;
            if ((__float_as_int(gi) ^ __float_as_int(gj)) >= 0) {
                DD = __fdividef(1.f, fabsf(gi) + fabsf(gj) + 1e-12f);
            } else {
                const float den = di - dsv[j];
                DD = __fdividef(gi - gj, den + copysignf(1e-12f, den));
            }
            An[i * STR + j] = (i == j) ? gi : Ac[i * STR + j] * DD;
        }
    }
    __syncthreads();

    // ---- GEMM: G = F_off * E  (2x4 register tile) ----
    const int i0  = (tid >> 4) * 2;
    const int j0g = (tid & 15) * 4;
    {
        float4 acc[2];
#pragma unroll
        for (int r = 0; r < 2; r++) acc[r] = make_float4(0.f, 0.f, 0.f, 0.f);
#pragma unroll 4
        for (int k = 0; k < DIM; k++) {
            const float4 e4 = *(const float4*)&Ac[k * STR + j0g];
#pragma unroll
            for (int r = 0; r < 2; r++) {
                const float bk = An[(i0 + r) * STR + k];
                acc[r].x = fmaf(bk, e4.x, acc[r].x);
                acc[r].y = fmaf(bk, e4.y, acc[r].y);
                acc[r].z = fmaf(bk, e4.z, acc[r].z);
                acc[r].w = fmaf(bk, e4.w, acc[r].w);
            }
        }
        // remove k==i (F diag) and k==j (A diag) contributions
#pragma unroll
        for (int r = 0; r < 2; r++) {
            const int i = i0 + r;
            const float gi = gs[i];
            const float4 arow = *(const float4*)&Ac[i * STR + j0g];
            acc[r].x -= gi * arow.x; acc[r].y -= gi * arow.y;
            acc[r].z -= gi * arow.z; acc[r].w -= gi * arow.w;
            float bv[4];
#pragma unroll
            for (int cc = 0; cc < 4; cc++) {
                const int j = j0g + cc;
                bv[cc] = (i == j) ? 0.f : An[i * STR + j];
            }
            acc[r].x -= bv[0] * dsv[j0g + 0];
            acc[r].y -= bv[1] * dsv[j0g + 1];
            acc[r].z -= bv[2] * dsv[j0g + 2];
            acc[r].w -= bv[3] * dsv[j0g + 3];
            *(float4*)&Gbuf[i * STR + j0g] = acc[r];
        }
    }
    __syncthreads();

    // ---- S: off-diagonal correction into An ----
    {
#pragma unroll
        for (int r = 0; r < 2; r++) {
            const int i = i0 + r;
            const float di = dsv[i];
#pragma unroll
            for (int cc = 0; cc < 4; cc++) {
                const int j = j0g + cc;
                if (i == j) continue;
                const float num = Gbuf[i * STR + j] - Gbuf[j * STR + i];
                const float den = di - dsv[j];
                float S = 0.f;
                if (fabsf(den) > 1e-3f * (fabsf(di) + fabsf(dsv[j]))) {
                    S = __fdividef(num, den);
                }
                An[i * STR + j] += S;
            }
        }
    }
    // ---- S: diagonal correction (8 threads per row) ----
    {
        const int i = tid >> 3;
        const int k0 = (tid & 7) * 8;
        const float di = dsv[i];
        const float agi = fabsf(gs[i]);
        float ssum = 0.f;
#pragma unroll
        for (int kk = k0; kk < k0 + 8; kk++) {
            if (kk == i) continue;
            const float e = Ac[i * STR + kk];
            const float dk = dsv[kk];
            const float agk = fabsf(gs[kk]);
            float w;
            if ((__float_as_int(di) ^ __float_as_int(dk)) >= 0) {
                const float t = agi + agk;
                w = -copysignf(__fdividef(1.f, 2.f * agi * t * t + 1e-20f), di);
            } else {
                const float den = di - dk;
                const float gij = __fdividef(gs[i] - gs[kk],
                                             den + copysignf(1e-20f, den));
                w = __fdividef(__fdividef(0.5f, agi + 1e-20f) - gij,
                               den + copysignf(1e-20f, den));
            }
            ssum = fmaf(e * e, w, ssum);
        }
        ssum += __shfl_xor_sync(0xffffffffu, ssum, 1);
        ssum += __shfl_xor_sync(0xffffffffu, ssum, 2);
        ssum += __shfl_xor_sync(0xffffffffu, ssum, 4);
        if ((tid & 7) == 0) An[i * STR + i] += ssum;
    }
    __syncthreads();

    // ---- GEMM1: T = F2 * Qt  -> Ac ----
    {
        float4 acc[2];
#pragma unroll
        for (int r = 0; r < 2; r++) acc[r] = make_float4(0.f, 0.f, 0.f, 0.f);
#pragma unroll 4
        for (int l = 0; l < DIM; l++) {
            const float4 q4 = *(const float4*)&Qts[l * STR + j0g];
#pragma unroll
            for (int r = 0; r < 2; r++) {
                const float fv = An[(i0 + r) * STR + l];
                acc[r].x = fmaf(fv, q4.x, acc[r].x);
                acc[r].y = fmaf(fv, q4.y, acc[r].y);
                acc[r].z = fmaf(fv, q4.z, acc[r].z);
                acc[r].w = fmaf(fv, q4.w, acc[r].w);
            }
        }
        __syncthreads();   // all reads of Ac (E) done before overwrite
#pragma unroll
        for (int r = 0; r < 2; r++)
            *(float4*)&Ac[(i0 + r) * STR + j0g] = acc[r];
    }
    __syncthreads();

    // ---- GEMM2: R = Qt^T * T; L2 normalize; write out ----
    {
        float4 acc[2];
#pragma unroll
        for (int r = 0; r < 2; r++) acc[r] = make_float4(0.f, 0.f, 0.f, 0.f);
#pragma unroll 4
        for (int k = 0; k < DIM; k++) {
            const float4 t4 = *(const float4*)&Ac[k * STR + j0g];
#pragma unroll
            for (int r = 0; r < 2; r++) {
                const float qv = Qts[k * STR + i0 + r];
                acc[r].x = fmaf(qv, t4.x, acc[r].x);
                acc[r].y = fmaf(qv, t4.y, acc[r].y);
                acc[r].z = fmaf(qv, t4.z, acc[r].z);
                acc[r].w = fmaf(qv, t4.w, acc[r].w);
            }
        }
        float ssq = 0.f;
#pragma unroll
        for (int r = 0; r < 2; r++)
            ssq += acc[r].x*acc[r].x + acc[r].y*acc[r].y
                 + acc[r].z*acc[r].z + acc[r].w*acc[r].w;
        const float total = block_reduce_sum(ssq, red, tid);
        const float scale = 1.f / fmaxf(sqrtf(total), 1e-12f);
#pragma unroll
        for (int r = 0; r < 2; r++) {
            acc[r].x *= scale; acc[r].y *= scale;
            acc[r].z *= scale; acc[r].w *= scale;
            *(float4*)(out + (size_t)b * (DIM * DIM) + (i0 + r) * DIM + j0g) = acc[r];
        }
    }
}

// ---------------------------------------------------------------------------
extern "C" void kernel_launch(void* const* d_in, const int* in_sizes, int n_in,
                              void* d_out, int out_size) {
    const float* x = (const float*)d_in[0];
    float* out = (float*)d_out;

    cudaFuncSetAttribute(sop_partial_max,
                         cudaFuncAttributeMaxDynamicSharedMemorySize,
                         PM_SMEM_BYTES);
    cudaFuncSetAttribute(sop_eig_kernel,
                         cudaFuncAttributeMaxDynamicSharedMemorySize,
                         EIG_SMEM_BYTES);

    sop_partial_max<<<dim3(SPLIT, BATCH), 256, PM_SMEM_BYTES>>>(x);
    sop_eig_kernel<<<BATCH, ETHREADS, EIG_SMEM_BYTES>>>(out);
}

// round 17
// speedup vs baseline: 1.0428x; 1.0428x over previous
#include <cuda_runtime.h>
#include <math.h>
#include <float.h>

#define BATCH 16
#define NPTS  2048
#define DIM   64
#define SPLIT 8
#define GROUPS 4
#define SPLIT_EFF (SPLIT * GROUPS)   // 32 partials per batch
#define CHUNK (NPTS / SPLIT)         // 256 rows per CTA
#define GROWS (CHUNK / GROUPS)       // 64 rows per group
#define STR 68
#define ETHREADS 512

#define EIG_SMEM_FLOATS (4 * DIM * STR)
#define EIG_SMEM_BYTES  (EIG_SMEM_FLOATS * 4)
#define PM_SMEM_BYTES   (CHUNK * DIM * 4)   // 64 KB

// scratch for partial maxima: 16 * 32 * 4096 * 4B = 8 MB
__device__ float g_partial[BATCH][SPLIT_EFF][DIM * DIM];

// ---------------------------------------------------------------------------
// Kernel 1: partial max of outer products. grid=(SPLIT,BATCH), 256 threads.
// ---------------------------------------------------------------------------
__global__ void __launch_bounds__(256) sop_partial_max(const float* __restrict__ x) {
    extern __shared__ float xs[];   // [CHUNK][DIM]
    const int b = blockIdx.y;
    const int c = blockIdx.x;
    const int tid = threadIdx.x;

    const float* xp = x + ((size_t)b * NPTS + (size_t)c * CHUNK) * DIM;
    for (int e = tid * 4; e < CHUNK * DIM; e += 256 * 4) {
        float4 v = *(const float4*)(xp + e);
        *(float4*)(xs + e) = v;
    }
    __syncthreads();

    const int g  = tid >> 6;
    const int gt = tid & 63;
    const int ti = (gt >> 3) * 8;
    const int tj = (gt & 7) * 8;
    const float* base = xs + g * GROWS * DIM;

    float acc[8][8];
#pragma unroll
    for (int a = 0; a < 8; a++)
#pragma unroll
        for (int bb = 0; bb < 8; bb++) acc[a][bb] = -FLT_MAX;

#pragma unroll 4
    for (int n = 0; n < GROWS; n++) {
        const float4 vi0 = *(const float4*)&base[n * DIM + ti];
        const float4 vi1 = *(const float4*)&base[n * DIM + ti + 4];
        const float4 vj0 = *(const float4*)&base[n * DIM + tj];
        const float4 vj1 = *(const float4*)&base[n * DIM + tj + 4];
        const float fi[8] = {vi0.x, vi0.y, vi0.z, vi0.w, vi1.x, vi1.y, vi1.z, vi1.w};
        const float fj[8] = {vj0.x, vj0.y, vj0.z, vj0.w, vj1.x, vj1.y, vj1.z, vj1.w};
#pragma unroll
        for (int a = 0; a < 8; a++)
#pragma unroll
            for (int bb = 0; bb < 8; bb++)
                acc[a][bb] = fmaxf(acc[a][bb], fi[a] * fj[bb]);
    }

    float* outp = g_partial[b][c * GROUPS + g];
#pragma unroll
    for (int a = 0; a < 8; a++) {
        *(float4*)(outp + (ti + a) * DIM + tj) =
            make_float4(acc[a][0], acc[a][1], acc[a][2], acc[a][3]);
        *(float4*)(outp + (ti + a) * DIM + tj + 4) =
            make_float4(acc[a][4], acc[a][5], acc[a][6], acc[a][7]);
    }
}

// ---------------------------------------------------------------------------
__device__ __forceinline__ float block_reduce_sum(float v, float* red, int tid) {
    __syncthreads();
#pragma unroll
    for (int o = 16; o; o >>= 1) v += __shfl_down_sync(0xffffffffu, v, o);
    if ((tid & 31) == 0) red[tid >> 5] = v;
    __syncthreads();
    if (tid < 32) {
        float w = (tid < 16) ? red[tid] : 0.f;
#pragma unroll
        for (int o = 8; o; o >>= 1) w += __shfl_down_sync(0xffffffffu, w, o);
        if (tid == 0) red[0] = w;
    }
    __syncthreads();
    return red[0];
}

__device__ __forceinline__ float offdiag_partial(const float* A, int tid) {
    const int e0 = tid * 8;
    const int i = e0 >> 6, j0 = e0 & 63;
    float off = 0.f;
#pragma unroll
    for (int u = 0; u < 8; u++) {
        const float v = A[i * STR + j0 + u];
        off += (i != j0 + u) ? v * v : 0.f;
    }
    return off;
}

// ---------------------------------------------------------------------------
// One Jacobi tournament round (R15 body): all smem loads issued up-front so
// they overlap the parameter MUFU chain; Qt stores issue before A stores;
// index advancement after stores (ptxas schedules it into the shadow).
// ---------------------------------------------------------------------------
struct JState {
    int pl, ql, plS, qlS;          // lane's column pair
    int pSA, qSA, pSB, qSB;        // warp's row-pair offsets
};

__device__ __forceinline__ void jacobi_round(
    const float* __restrict__ Ac, float* __restrict__ An,
    float* __restrict__ Qts, JState& st, int warp, int lane)
{
    // ======== front-loaded loads (all ready at round start) ========
    const float app = Ac[st.plS + st.pl];
    const float aqq = Ac[st.qlS + st.ql];
    const float apq = Ac[st.plS + st.ql];

    const float aA_pp = Ac[st.pSA + st.pl];
    const float aA_pq = Ac[st.pSA + st.ql];
    const float aA_qp = Ac[st.qSA + st.pl];
    const float aA_qq = Ac[st.qSA + st.ql];

    const float aB_pp = Ac[st.pSB + st.pl];
    const float aB_pq = Ac[st.pSB + st.ql];
    const float aB_qp = Ac[st.qSB + st.pl];
    const float aB_qq = Ac[st.qSB + st.ql];

    const int   pSq = (lane < 16) ? st.pSA : st.pSB;
    const int   qSq = (lane < 16) ? st.qSA : st.qSB;
    const int   sub = (lane & 15) * 4;
    float4* Qp = (float4*)(Qts + pSq + sub);
    float4* Qq = (float4*)(Qts + qSq + sub);
    const float4 qp = *Qp;
    const float4 qq = *Qq;

    // ======== rotation params for column pair 'lane' (2 MUFU) ========
    const float d = aqq - app;
    const float g = apq + apq;
    const float rr = fmaf(d, d, g * g);
    const float ir = __frsqrt_rn(rr);
    const float xv = fabsf(d) * ir;
    const float yv = fmaf(0.5f, xv, 0.5f);
    const float ic = __frsqrt_rn(yv);
    float c = yv * ic;
    float s = 0.5f * g * ir * ic;
    s = __int_as_float(__float_as_int(s) ^
                       (__float_as_int(d) & 0x80000000));
    if (rr < 1e-40f) { c = 1.f; s = 0.f; }

    // row-pair params via shfl
    const float cA = __shfl_sync(0xffffffffu, c, warp);
    const float sA = __shfl_sync(0xffffffffu, s, warp);
    const float cB = __shfl_sync(0xffffffffu, c, warp + 16);
    const float sB = __shfl_sync(0xffffffffu, s, warp + 16);

    // ======== Qt update + stores FIRST (early drain) ========
    {
        const float cq = (lane < 16) ? cA : cB;
        const float sq = (lane < 16) ? sA : sB;
        *Qp = make_float4(fmaf(cq, qp.x, -sq * qq.x),
                          fmaf(cq, qp.y, -sq * qq.y),
                          fmaf(cq, qp.z, -sq * qq.z),
                          fmaf(cq, qp.w, -sq * qq.w));
        *Qq = make_float4(fmaf(sq, qp.x, cq * qq.x),
                          fmaf(sq, qp.y, cq * qq.y),
                          fmaf(sq, qp.z, cq * qq.z),
                          fmaf(sq, qp.w, cq * qq.w));
    }

    // ======== A: fused two-sided 2x2 updates (reg-resident inputs) ========
    {
        const float rp_p = fmaf(cA, aA_pp, -sA * aA_qp);
        const float rp_q = fmaf(cA, aA_pq, -sA * aA_qq);
        const float rq_p = fmaf(sA, aA_pp,  cA * aA_qp);
        const float rq_q = fmaf(sA, aA_pq,  cA * aA_qq);
        An[st.pSA + st.pl] = fmaf(c, rp_p, -s * rp_q);
        An[st.pSA + st.ql] = fmaf(s, rp_p,  c * rp_q);
        An[st.qSA + st.pl] = fmaf(c, rq_p, -s * rq_q);
        An[st.qSA + st.ql] = fmaf(s, rq_p,  c * rq_q);
    }
    {
        const float rp_p = fmaf(cB, aB_pp, -sB * aB_qp);
        const float rp_q = fmaf(cB, aB_pq, -sB * aB_qq);
        const float rq_p = fmaf(sB, aB_pp,  cB * aB_qp);
        const float rq_q = fmaf(sB, aB_pq,  cB * aB_qq);
        An[st.pSB + st.pl] = fmaf(c, rp_p, -s * rp_q);
        An[st.pSB + st.ql] = fmaf(s, rp_p,  c * rp_q);
        An[st.qSB + st.pl] = fmaf(c, rq_p, -s * rq_q);
        An[st.qSB + st.ql] = fmaf(s, rq_p,  c * rq_q);
    }

    // ======== advance indices (+1 mod 63; pair-0 keeps p = 63) ========
    if (lane) {
        st.pl  = (st.pl  == 62)       ? 0 : st.pl + 1;
        st.plS = (st.plS == 62 * STR) ? 0 : st.plS + STR;
    }
    st.ql  = (st.ql  == 62)       ? 0 : st.ql + 1;
    st.qlS = (st.qlS == 62 * STR) ? 0 : st.qlS + STR;
    if (warp) st.pSA = (st.pSA == 62 * STR) ? 0 : st.pSA + STR;
    st.qSA = (st.qSA == 62 * STR) ? 0 : st.qSA + STR;
    st.pSB = (st.pSB == 62 * STR) ? 0 : st.pSB + STR;
    st.qSB = (st.qSB == 62 * STR) ? 0 : st.qSB + STR;

    __syncthreads();
}

// ---------------------------------------------------------------------------
// Kernel 2: 4 Jacobi sweeps + segmented valve 5th sweep (checks every 8
// rounds), 2nd-order Daleckii-Krein sqrt, Qt^T F2 Qt, L2 normalize.
// 512 threads / 16 warps, one CTA per batch.
// ---------------------------------------------------------------------------
__global__ void __launch_bounds__(ETHREADS) sop_eig_kernel(float* __restrict__ out) {
    extern __shared__ float dsm[];
    float* Abuf0 = dsm;
    float* Abuf1 = dsm + DIM * STR;
    float* Qts   = dsm + 2 * DIM * STR;
    float* Gbuf  = dsm + 3 * DIM * STR;

    __shared__ float red[16];
    __shared__ float gs[DIM];
    __shared__ float dsv[DIM];

    const int b = blockIdx.x;
    const int tid = threadIdx.x;
    const int warp = tid >> 5;
    const int lane = tid & 31;

    // ---- reduce partials into A0 (float4), init Qt = I, accumulate frob2 ----
    float frloc = 0.f;
    {
        const int e0 = tid * 8;
        const int i = e0 >> 6, j0 = e0 & 63;
        float4 m0 = make_float4(-FLT_MAX, -FLT_MAX, -FLT_MAX, -FLT_MAX);
        float4 m1 = m0;
#pragma unroll 8
        for (int c = 0; c < SPLIT_EFF; c++) {
            const float4* gp = (const float4*)&g_partial[b][c][e0];
            float4 v0 = gp[0], v1 = gp[1];
            m0.x = fmaxf(m0.x, v0.x); m0.y = fmaxf(m0.y, v0.y);
            m0.z = fmaxf(m0.z, v0.z); m0.w = fmaxf(m0.w, v0.w);
            m1.x = fmaxf(m1.x, v1.x); m1.y = fmaxf(m1.y, v1.y);
            m1.z = fmaxf(m1.z, v1.z); m1.w = fmaxf(m1.w, v1.w);
        }
        *(float4*)&Abuf0[i * STR + j0]     = m0;
        *(float4*)&Abuf0[i * STR + j0 + 4] = m1;
        frloc = m0.x*m0.x + m0.y*m0.y + m0.z*m0.z + m0.w*m0.w
              + m1.x*m1.x + m1.y*m1.y + m1.z*m1.z + m1.w*m1.w;
        float4 id0 = make_float4((i == j0+0)?1.f:0.f, (i == j0+1)?1.f:0.f,
                                 (i == j0+2)?1.f:0.f, (i == j0+3)?1.f:0.f);
        float4 id1 = make_float4((i == j0+4)?1.f:0.f, (i == j0+5)?1.f:0.f,
                                 (i == j0+6)?1.f:0.f, (i == j0+7)?1.f:0.f);
        *(float4*)&Qts[i * STR + j0]     = id0;
        *(float4*)&Qts[i * STR + j0 + 4] = id1;
    }
    const float frob2 = block_reduce_sum(frloc, red, tid) + 1e-30f;

    // ---- persistent tournament indices ----
    JState st;
    if (lane == 0) { st.pl = 63; st.ql = 0; }
    else           { st.pl = lane; st.ql = 63 - lane; }
    st.plS = st.pl * STR;
    st.qlS = st.ql * STR;
    if (warp == 0) { st.pSA = 63 * STR; st.qSA = 0; }
    else           { st.pSA = warp * STR; st.qSA = (63 - warp) * STR; }
    st.pSB = (warp + 16) * STR;
    st.qSB = (47 - warp) * STR;

    // ---- 4 sweeps = 252 rounds (even), unrolled x2; ends in Abuf0 ----
    for (int rp = 0; rp < 126; rp++) {
        jacobi_round(Abuf0, Abuf1, Qts, st, warp, lane);
        jacobi_round(Abuf1, Abuf0, Qts, st, warp, lane);
    }

    // ---- valve: segmented 5th sweep (check every 8 rounds) ----
    float* Ac = Abuf0;
    float* An = Abuf1;
    {
        const float thr = 3e-5f * frob2;
        const float offt = block_reduce_sum(offdiag_partial(Ac, tid), red, tid);
        if (offt >= thr) {
            int done = 0;
#pragma unroll 1
            for (int seg = 0; seg < 8; seg++) {
                const int stop = (seg == 7) ? 63 : 8 * (seg + 1);
#pragma unroll 1
                for (; done < stop; done++) {
                    jacobi_round(Ac, An, Qts, st, warp, lane);
                    float* t = Ac; Ac = An; An = t;
                }
                const float o2 = block_reduce_sum(offdiag_partial(Ac, tid),
                                                  red, tid);
                if (o2 < thr) break;
            }
        }
    }

    // =======================================================================
    // 2nd-order Daleckii-Krein sqrt of A = D + E, msqrt = Qt^T (F+S) Qt
    // =======================================================================

    if (tid < DIM) {
        const float lam = Ac[tid * STR + tid];
        dsv[tid] = lam;
        gs[tid] = copysignf(sqrtf(fabsf(lam)), lam);
    }
    __syncthreads();

    // ---- build F into An (thread: row i, 8 cols) ----
    {
        const int i = tid >> 3;
        const int j0 = (tid & 7) * 8;
        const float gi = gs[i];
        const float di = dsv[i];
#pragma unroll
        for (int u = 0; u < 8; u++) {
            const int j = j0 + u;
            const float gj = gs[j];
            float DD;
            if ((__float_as_int(gi) ^ __float_as_int(gj)) >= 0) {
                DD = __fdividef(1.f, fabsf(gi) + fabsf(gj) + 1e-12f);
            } else {
                const float den = di - dsv[j];
                DD = __fdividef(gi - gj, den + copysignf(1e-12f, den));
            }
            An[i * STR + j] = (i == j) ? gi : Ac[i * STR + j] * DD;
        }
    }
    __syncthreads();

    // ---- GEMM: G = F_off * E  (2x4 register tile) ----
    const int i0  = (tid >> 4) * 2;
    const int j0g = (tid & 15) * 4;
    {
        float4 acc[2];
#pragma unroll
        for (int r = 0; r < 2; r++) acc[r] = make_float4(0.f, 0.f, 0.f, 0.f);
#pragma unroll 4
        for (int k = 0; k < DIM; k++) {
            const float4 e4 = *(const float4*)&Ac[k * STR + j0g];
#pragma unroll
            for (int r = 0; r < 2; r++) {
                const float bk = An[(i0 + r) * STR + k];
                acc[r].x = fmaf(bk, e4.x, acc[r].x);
                acc[r].y = fmaf(bk, e4.y, acc[r].y);
                acc[r].z = fmaf(bk, e4.z, acc[r].z);
                acc[r].w = fmaf(bk, e4.w, acc[r].w);
            }
        }
        // remove k==i (F diag) and k==j (A diag) contributions
#pragma unroll
        for (int r = 0; r < 2; r++) {
            const int i = i0 + r;
            const float gi = gs[i];
            const float4 arow = *(const float4*)&Ac[i * STR + j0g];
            acc[r].x -= gi * arow.x; acc[r].y -= gi * arow.y;
            acc[r].z -= gi * arow.z; acc[r].w -= gi * arow.w;
            float bv[4];
#pragma unroll
            for (int cc = 0; cc < 4; cc++) {
                const int j = j0g + cc;
                bv[cc] = (i == j) ? 0.f : An[i * STR + j];
            }
            acc[r].x -= bv[0] * dsv[j0g + 0];
            acc[r].y -= bv[1] * dsv[j0g + 1];
            acc[r].z -= bv[2] * dsv[j0g + 2];
            acc[r].w -= bv[3] * dsv[j0g + 3];
            *(float4*)&Gbuf[i * STR + j0g] = acc[r];
        }
    }
    __syncthreads();

    // ---- S: off-diagonal correction into An ----
    {
#pragma unroll
        for (int r = 0; r < 2; r++) {
            const int i = i0 + r;
            const float di = dsv[i];
#pragma unroll
            for (int cc = 0; cc < 4; cc++) {
                const int j = j0g + cc;
                if (i == j) continue;
                const float num = Gbuf[i * STR + j] - Gbuf[j * STR + i];
                const float den = di - dsv[j];
                float S = 0.f;
                if (fabsf(den) > 1e-3f * (fabsf(di) + fabsf(dsv[j]))) {
                    S = __fdividef(num, den);
                }
                An[i * STR + j] += S;
            }
        }
    }
    // ---- S: diagonal correction (8 threads per row) ----
    {
        const int i = tid >> 3;
        const int k0 = (tid & 7) * 8;
        const float di = dsv[i];
        const float agi = fabsf(gs[i]);
        float ssum = 0.f;
#pragma unroll
        for (int kk = k0; kk < k0 + 8; kk++) {
            if (kk == i) continue;
            const float e = Ac[i * STR + kk];
            const float dk = dsv[kk];
            const float agk = fabsf(gs[kk]);
            float w;
            if ((__float_as_int(di) ^ __float_as_int(dk)) >= 0) {
                const float t = agi + agk;
                w = -copysignf(__fdividef(1.f, 2.f * agi * t * t + 1e-20f), di);
            } else {
                const float den = di - dk;
                const float gij = __fdividef(gs[i] - gs[kk],
                                             den + copysignf(1e-20f, den));
                w = __fdividef(__fdividef(0.5f, agi + 1e-20f) - gij,
                               den + copysignf(1e-20f, den));
            }
            ssum = fmaf(e * e, w, ssum);
        }
        ssum += __shfl_xor_sync(0xffffffffu, ssum, 1);
        ssum += __shfl_xor_sync(0xffffffffu, ssum, 2);
        ssum += __shfl_xor_sync(0xffffffffu, ssum, 4);
        if ((tid & 7) == 0) An[i * STR + i] += ssum;
    }
    __syncthreads();

    // ---- GEMM1: T = F2 * Qt  -> Ac ----
    {
        float4 acc[2];
#pragma unroll
        for (int r = 0; r < 2; r++) acc[r] = make_float4(0.f, 0.f, 0.f, 0.f);
#pragma unroll 4
        for (int l = 0; l < DIM; l++) {
            const float4 q4 = *(const float4*)&Qts[l * STR + j0g];
#pragma unroll
            for (int r = 0; r < 2; r++) {
                const float fv = An[(i0 + r) * STR + l];
                acc[r].x = fmaf(fv, q4.x, acc[r].x);
                acc[r].y = fmaf(fv, q4.y, acc[r].y);
                acc[r].z = fmaf(fv, q4.z, acc[r].z);
                acc[r].w = fmaf(fv, q4.w, acc[r].w);
            }
        }
        __syncthreads();   // all reads of Ac (E) done before overwrite
#pragma unroll
        for (int r = 0; r < 2; r++)
            *(float4*)&Ac[(i0 + r) * STR + j0g] = acc[r];
    }
    __syncthreads();

    // ---- GEMM2: R = Qt^T * T; L2 normalize; write out ----
    {
        float4 acc[2];
#pragma unroll
        for (int r = 0; r < 2; r++) acc[r] = make_float4(0.f, 0.f, 0.f, 0.f);
#pragma unroll 4
        for (int k = 0; k < DIM; k++) {
            const float4 t4 = *(const float4*)&Ac[k * STR + j0g];
#pragma unroll
            for (int r = 0; r < 2; r++) {
                const float qv = Qts[k * STR + i0 + r];
                acc[r].x = fmaf(qv, t4.x, acc[r].x);
                acc[r].y = fmaf(qv, t4.y, acc[r].y);
                acc[r].z = fmaf(qv, t4.z, acc[r].z);
                acc[r].w = fmaf(qv, t4.w, acc[r].w);
            }
        }
        float ssq = 0.f;
#pragma unroll
        for (int r = 0; r < 2; r++)
            ssq += acc[r].x*acc[r].x + acc[r].y*acc[r].y
                 + acc[r].z*acc[r].z + acc[r].w*acc[r].w;
        const float total = block_reduce_sum(ssq, red, tid);
        const float scale = 1.f / fmaxf(sqrtf(total), 1e-12f);
#pragma unroll
        for (int r = 0; r < 2; r++) {
            acc[r].x *= scale; acc[r].y *= scale;
            acc[r].z *= scale; acc[r].w *= scale;
            *(float4*)(out + (size_t)b * (DIM * DIM) + (i0 + r) * DIM + j0g) = acc[r];
        }
    }
}

// ---------------------------------------------------------------------------
extern "C" void kernel_launch(void* const* d_in, const int* in_sizes, int n_in,
                              void* d_out, int out_size) {
    const float* x = (const float*)d_in[0];
    float* out = (float*)d_out;

    cudaFuncSetAttribute(sop_partial_max,
                         cudaFuncAttributeMaxDynamicSharedMemorySize,
                         PM_SMEM_BYTES);
    cudaFuncSetAttribute(sop_eig_kernel,
                         cudaFuncAttributeMaxDynamicSharedMemorySize,
                         EIG_SMEM_BYTES);

    sop_partial_max<<<dim3(SPLIT, BATCH), 256, PM_SMEM_BYTES>>>(x);
    sop_eig_kernel<<<BATCH, ETHREADS, EIG_SMEM_BYTES>>>(out);
}